// round 6
// baseline (speedup 1.0000x reference)
#include <cuda_runtime.h>

// Per-token qlayer outputs, [B*S*64] = 131072 floats.
__device__ float g_q[4 * 512 * 64];

// ===========================================================================
// Kernel A: closed-form qlayer (Pauli-transfer contraction, validated R4/R5).
// One thread per token; 256 blocks x 64 threads; fast __sincosf for the 8
// per-token angles (inputs are O(+-5): fast path accurate to ~2^-21).
// ===========================================================================
__global__ void __launch_bounds__(64) qsim_closed(const float* __restrict__ x,
                                                  const float* __restrict__ prx,
                                                  const float* __restrict__ prz) {
    __shared__ float s_rx0[8], s_sf[8], s_cf[8], s_c1[8], s_s1[8];
    int tid = threadIdx.x;
    if (tid < 8) {
        s_rx0[tid] = prx[tid];
        float s, c; sincosf(prz[tid], &s, &c);   // params: accurate path (once/block)
        s_sf[tid] = s; s_cf[tid] = c;
    } else if (tid < 16) {
        int i = tid - 8;
        float s, c; sincosf(prx[8 + i], &s, &c);
        s_s1[i] = s; s_c1[i] = c;
    }
    __syncthreads();

    int t = blockIdx.x * 64 + tid;
    const float4* xp = reinterpret_cast<const float4*>(x + t * 8);
    float4 xa = __ldg(xp), xb = __ldg(xp + 1);
    float xv[8] = {xa.x, xa.y, xa.z, xa.w, xb.x, xb.y, xb.z, xb.w};

    float vx[8], vy[8], vz[8];
#pragma unroll
    for (int w = 0; w < 8; w++) {
        float st, ct;
        __sincosf(xv[w] + s_rx0[w], &st, &ct);   // fast MUFU path
        vz[w] = ct;
        vx[w] = st * s_sf[w];
        vy[w] = -st * s_cf[w];
    }

    // A_0: state after CNOT(0,1); rows = pending wire-0 Pauli, cols = carry
    float A[4][4];
    A[0][0] = 1.f;            A[0][1] = vx[1];          A[0][2] = vz[0] * vy[1];  A[0][3] = vz[0] * vz[1];
    A[1][0] = vx[0] * vx[1];  A[1][1] = vx[0];          A[1][2] = vy[0] * vz[1];  A[1][3] = -vy[0] * vy[1];
    A[2][0] = vy[0] * vx[1];  A[2][1] = vy[0];          A[2][2] = -vx[0] * vz[1]; A[2][3] = vx[0] * vy[1];
    A[3][0] = vz[0];          A[3][1] = vz[0] * vx[1];  A[3][2] = vy[1];          A[3][3] = vz[1];

    float Zt[7];
    Zt[6] = 1.f;
#pragma unroll
    for (int k = 5; k >= 1; k--) Zt[k] = Zt[k + 1] * vz[k + 2];

    float q[8];
    float c10 = s_c1[0], s10 = s_s1[0];
#pragma unroll
    for (int w = 1; w <= 6; w++) {
        float cc = s_c1[w], ss = s_s1[w];
        float xn = vx[w + 1], yn = vy[w + 1], zn = vz[w + 1];
        float cx = cc * xn, cy = cc * yn, cz = cc * zn;
        float sx = ss * xn, sy = ss * yn, sz = ss * zn;
#pragma unroll
        for (int r = 0; r < 4; r++) {
            float aI = A[r][0], aX = A[r][1], aY = A[r][2], aZ = A[r][3];
            A[r][0] = cc * aZ + sx * aY;
            A[r][1] = cx * aZ + ss * aY;
            A[r][2] = cy * aI - sz * aX;
            A[r][3] = cz * aI + sy * aX;
        }
        q[w] = Zt[w] * (s10 * A[2][3] + c10 * A[3][3]);
    }
    float c17 = s_c1[7], s17 = s_s1[7];
    q[7] = c17 * (s10 * A[2][0] + c10 * A[3][0]) + s17 * (c10 * A[2][1] - s10 * A[3][1]);
    q[0] = c17 * A[0][3] + s17 * A[1][2];

    float4* o = reinterpret_cast<float4*>(g_q + t * 8);
    o[0] = make_float4(q[0], q[1], q[2], q[3]);
    o[1] = make_float4(q[4], q[5], q[6], q[7]);
}

// ===========================================================================
// Kernel B: out[r][j] = sum_k q[r][k] * W[j][k].  256 blocks x 256 threads
// (2048 warps -> latency hidden). Block = 8 rows; W staged in shared with the
// conflict-free 17-float4 padded layout; each thread computes 2 outputs.
// ===========================================================================
__global__ void __launch_bounds__(256) combine_kernel(const float* __restrict__ W,
                                                      float* __restrict__ out) {
    __shared__ float Ws[64 * 68];   // float4 view: row j at [j*17 + c], c=0..15
    __shared__ float qs[512];       // 8 rows x 64
    int tid = threadIdx.x;

    const float4* Wg = reinterpret_cast<const float4*>(W);
#pragma unroll
    for (int i = 0; i < 4; i++) {
        int m = tid + i * 256;          // float4 index 0..1023
        int j = m >> 4, c = m & 15;
        reinterpret_cast<float4*>(Ws)[j * 17 + c] = __ldg(Wg + m);
    }
    if (tid < 128)
        reinterpret_cast<float4*>(qs)[tid] =
            __ldg(reinterpret_cast<const float4*>(g_q + blockIdx.x * 512) + tid);
    __syncthreads();

    int j = tid & 63, rp = tid >> 6;    // rp = row-pair 0..3
    const float4* wrow = reinterpret_cast<const float4*>(Ws) + j * 17;
    const float4* qa = reinterpret_cast<const float4*>(qs) + (rp * 2) * 16;
    const float4* qb = qa + 16;

    float acc0 = 0.f, acc1 = 0.f;
#pragma unroll
    for (int c = 0; c < 16; c++) {
        float4 wv = wrow[c];
        float4 a = qa[c], b = qb[c];
        acc0 = fmaf(a.x, wv.x, fmaf(a.y, wv.y, fmaf(a.z, wv.z, fmaf(a.w, wv.w, acc0))));
        acc1 = fmaf(b.x, wv.x, fmaf(b.y, wv.y, fmaf(b.z, wv.z, fmaf(b.w, wv.w, acc1))));
    }
    int row0 = blockIdx.x * 8 + rp * 2;
    out[row0 * 64 + j]       = acc0;
    out[(row0 + 1) * 64 + j] = acc1;
}

extern "C" void kernel_launch(void* const* d_in, const int* in_sizes, int n_in,
                              void* d_out, int out_size) {
    const float* x   = (const float*)d_in[0];
    const float* prx = (const float*)d_in[1];
    const float* prz = (const float*)d_in[2];
    const float* W   = (const float*)d_in[3];
    float* out = (float*)d_out;

    int n_tok = in_sizes[0] / 8;                         // 16384 tokens
    qsim_closed<<<n_tok / 64, 64>>>(x, prx, prz);        // 256 blocks x 64
    combine_kernel<<<n_tok / 64, 256>>>(W, out);         // 256 blocks x 256
}

// round 7
// speedup vs baseline: 1.2389x; 1.2389x over previous
#include <cuda_runtime.h>

// ===========================================================================
// Fully fused, single-wave kernel. 128 blocks x 128 threads = 16384 threads,
// exactly one per token; block = 128 tokens = 16 (b,s) rows.
//   Phase 0: LDG W into registers (8 float4/thread; latency hidden by phase 1)
//   Phase 1: closed-form qlayer per token (Pauli-transfer sweep, R4-validated)
//   Phase 2: out[r][j] = sum_k q[r][k]*W[j][k], W in swizzled shared
// ===========================================================================
__global__ void __launch_bounds__(128) qmha_fused(const float* __restrict__ x,
                                                  const float* __restrict__ prx,
                                                  const float* __restrict__ prz,
                                                  const float* __restrict__ W,
                                                  float* __restrict__ out) {
    __shared__ float s_rx0[8], s_sf[8], s_cf[8], s_c1[8], s_s1[8];
    __shared__ float4 Ws4[1024];   // W float4 (j,c) at slot j*16 + (c ^ (j&7))
    __shared__ float qs[1024];     // 16 rows x 64

    int tid = threadIdx.x;

    // ---- Phase 0: W loads into registers (coalesced, MLP 8) ----
    const float4* Wg = reinterpret_cast<const float4*>(W);
    float4 wreg[8];
#pragma unroll
    for (int i = 0; i < 8; i++) wreg[i] = __ldg(Wg + tid + i * 128);

    if (tid < 8) {
        s_rx0[tid] = prx[tid];
        float s, c; sincosf(prz[tid], &s, &c);    // layer-0 RZ (full angle)
        s_sf[tid] = s; s_cf[tid] = c;
    } else if (tid < 16) {
        int i = tid - 8;
        float s, c; sincosf(prx[8 + i], &s, &c);  // layer-1 RX (full angle)
        s_s1[i] = s; s_c1[i] = c;
    }
    __syncthreads();   // params visible

    // ---- Phase 1: closed-form q for this thread's token ----
    int t = blockIdx.x * 128 + tid;
    const float4* xp = reinterpret_cast<const float4*>(x + t * 8);
    float4 xa = __ldg(xp), xb = __ldg(xp + 1);
    float xv[8] = {xa.x, xa.y, xa.z, xa.w, xb.x, xb.y, xb.z, xb.w};

    float vx[8], vy[8], vz[8];
#pragma unroll
    for (int w = 0; w < 8; w++) {
        float st, ct;
        __sincosf(xv[w] + s_rx0[w], &st, &ct);    // fast MUFU path (validated R6)
        vz[w] = ct;
        vx[w] = st * s_sf[w];
        vy[w] = -st * s_cf[w];
    }

    // A_0: state after CNOT(0,1); rows = pending wire-0 Pauli, cols = carry
    float A[4][4];
    A[0][0] = 1.f;            A[0][1] = vx[1];          A[0][2] = vz[0] * vy[1];  A[0][3] = vz[0] * vz[1];
    A[1][0] = vx[0] * vx[1];  A[1][1] = vx[0];          A[1][2] = vy[0] * vz[1];  A[1][3] = -vy[0] * vy[1];
    A[2][0] = vy[0] * vx[1];  A[2][1] = vy[0];          A[2][2] = -vx[0] * vz[1]; A[2][3] = vx[0] * vy[1];
    A[3][0] = vz[0];          A[3][1] = vz[0] * vx[1];  A[3][2] = vy[1];          A[3][3] = vz[1];

    float Zt[7];
    Zt[6] = 1.f;
#pragma unroll
    for (int k = 5; k >= 1; k--) Zt[k] = Zt[k + 1] * vz[k + 2];

    float q[8];
    float c10 = s_c1[0], s10 = s_s1[0];
#pragma unroll
    for (int w = 1; w <= 6; w++) {
        float cc = s_c1[w], ss = s_s1[w];
        float xn = vx[w + 1], yn = vy[w + 1], zn = vz[w + 1];
        float cx = cc * xn, cy = cc * yn, cz = cc * zn;
        float sx = ss * xn, sy = ss * yn, sz = ss * zn;
#pragma unroll
        for (int r = 0; r < 4; r++) {
            float aI = A[r][0], aX = A[r][1], aY = A[r][2], aZ = A[r][3];
            A[r][0] = cc * aZ + sx * aY;
            A[r][1] = cx * aZ + ss * aY;
            A[r][2] = cy * aI - sz * aX;
            A[r][3] = cz * aI + sy * aX;
        }
        q[w] = Zt[w] * (s10 * A[2][3] + c10 * A[3][3]);
    }
    float c17 = s_c1[7], s17 = s_s1[7];
    q[7] = c17 * (s10 * A[2][0] + c10 * A[3][0]) + s17 * (c10 * A[2][1] - s10 * A[3][1]);
    q[0] = c17 * A[0][3] + s17 * A[1][2];

    // qs[tid*8 + w] == row-major [row_local = tid/8][k = (tid%8)*8 + w]
    float4* qo = reinterpret_cast<float4*>(qs + tid * 8);
    qo[0] = make_float4(q[0], q[1], q[2], q[3]);
    qo[1] = make_float4(q[4], q[5], q[6], q[7]);

    // Park W into swizzled shared (W latency has been hidden by phase 1)
#pragma unroll
    for (int i = 0; i < 8; i++) {
        int m = tid + i * 128;           // float4 index = j*16 + c
        int j = m >> 4, c = m & 15;
        Ws4[j * 16 + (c ^ (j & 7))] = wreg[i];
    }
    __syncthreads();

    // ---- Phase 2: 8 outputs per thread ----
    int j = tid & 63, g = tid >> 6;      // col j; rows g*8 .. g*8+7
    const float4* q4 = reinterpret_cast<const float4*>(qs) + g * 8 * 16;

    float acc[8] = {0.f, 0.f, 0.f, 0.f, 0.f, 0.f, 0.f, 0.f};
#pragma unroll
    for (int c = 0; c < 16; c++) {
        float4 wv = Ws4[j * 16 + (c ^ (j & 7))];   // conflict-free (swizzled)
#pragma unroll
        for (int r = 0; r < 8; r++) {
            float4 a = q4[r * 16 + c];             // broadcast within warp
            acc[r] = fmaf(a.x, wv.x, fmaf(a.y, wv.y, fmaf(a.z, wv.z, fmaf(a.w, wv.w, acc[r]))));
        }
    }
    int row0 = blockIdx.x * 16 + g * 8;
#pragma unroll
    for (int r = 0; r < 8; r++)
        out[(row0 + r) * 64 + j] = acc[r];
}

extern "C" void kernel_launch(void* const* d_in, const int* in_sizes, int n_in,
                              void* d_out, int out_size) {
    const float* x   = (const float*)d_in[0];
    const float* prx = (const float*)d_in[1];
    const float* prz = (const float*)d_in[2];
    const float* W   = (const float*)d_in[3];
    float* out = (float*)d_out;

    int n_tok = in_sizes[0] / 8;                    // 16384 tokens
    qmha_fused<<<n_tok / 128, 128>>>(x, prx, prz, W, out);  // 128 blocks, 1 wave
}

// round 8
// speedup vs baseline: 1.2785x; 1.0320x over previous
#include <cuda_runtime.h>

typedef unsigned long long ull;

__device__ __forceinline__ ull pk(float lo, float hi) {
    ull r; asm("mov.b64 %0, {%1,%2};" : "=l"(r) : "f"(lo), "f"(hi)); return r;
}
__device__ __forceinline__ void upk(ull v, float &lo, float &hi) {
    asm("mov.b64 {%0,%1}, %2;" : "=f"(lo), "=f"(hi) : "l"(v));
}
__device__ __forceinline__ ull f2fma(ull a, ull b, ull c) {
    ull d; asm("fma.rn.f32x2 %0,%1,%2,%3;" : "=l"(d) : "l"(a), "l"(b), "l"(c)); return d;
}

// ===========================================================================
// Fused single-wave kernel, warp-specialized. 128 blocks x 256 threads.
//   warps 0-3 : 1 token/thread -> closed-form q (Pauli sweep, R4-validated)
//   warps 4-7 : W LDG -> swizzled shared ; params via fast __sincosf
//   phase 2   : all 8 warps, f32x2 packed dot products
// ===========================================================================
__global__ void __launch_bounds__(256) qmha_fused(const float* __restrict__ x,
                                                  const float* __restrict__ prx,
                                                  const float* __restrict__ prz,
                                                  const float* __restrict__ W,
                                                  float* __restrict__ out) {
    __shared__ float s_rx0[8], s_sf[8], s_cf[8], s_c1[8], s_s1[8];
    __shared__ float4 Ws4[1024];   // W float4 (j,c) at slot j*16 + (c ^ (j&7))
    __shared__ float qs[1024];     // 16 rows x 64

    int tid = threadIdx.x;
    float4 xa, xb;
    float4 wreg[8];

    if (tid < 128) {
        // token threads: get x in flight immediately
        int t = blockIdx.x * 128 + tid;
        const float4* xp = reinterpret_cast<const float4*>(x + t * 8);
        xa = __ldg(xp); xb = __ldg(xp + 1);
    } else {
        int wt = tid - 128;
        const float4* Wg = reinterpret_cast<const float4*>(W);
#pragma unroll
        for (int i = 0; i < 8; i++) wreg[i] = __ldg(Wg + wt + i * 128);
        if (wt < 8) {
            s_rx0[wt] = __ldg(prx + wt);
            float s, c; __sincosf(__ldg(prz + wt), &s, &c);    // layer-0 RZ
            s_sf[wt] = s; s_cf[wt] = c;
        } else if (wt < 16) {
            int i = wt - 8;
            float s, c; __sincosf(__ldg(prx + 8 + i), &s, &c); // layer-1 RX
            s_s1[i] = s; s_c1[i] = c;
        }
    }
    __syncthreads();   // params ready

    if (tid < 128) {
        // ---- Phase 1: closed-form q for this thread's token ----
        float xv[8] = {xa.x, xa.y, xa.z, xa.w, xb.x, xb.y, xb.z, xb.w};
        float vx[8], vy[8], vz[8];
#pragma unroll
        for (int w = 0; w < 8; w++) {
            float st, ct;
            __sincosf(xv[w] + s_rx0[w], &st, &ct);
            vz[w] = ct;
            vx[w] = st * s_sf[w];
            vy[w] = -st * s_cf[w];
        }

        // A_0: after CNOT(0,1); rows = pending wire-0 Pauli, cols = carry
        float A[4][4];
        A[0][0] = 1.f;            A[0][1] = vx[1];          A[0][2] = vz[0] * vy[1];  A[0][3] = vz[0] * vz[1];
        A[1][0] = vx[0] * vx[1];  A[1][1] = vx[0];          A[1][2] = vy[0] * vz[1];  A[1][3] = -vy[0] * vy[1];
        A[2][0] = vy[0] * vx[1];  A[2][1] = vy[0];          A[2][2] = -vx[0] * vz[1]; A[2][3] = vx[0] * vy[1];
        A[3][0] = vz[0];          A[3][1] = vz[0] * vx[1];  A[3][2] = vy[1];          A[3][3] = vz[1];

        float Zt[7];
        Zt[6] = 1.f;
#pragma unroll
        for (int k = 5; k >= 1; k--) Zt[k] = Zt[k + 1] * vz[k + 2];

        float q[8];
        float c10 = s_c1[0], s10 = s_s1[0];
#pragma unroll
        for (int w = 1; w <= 6; w++) {
            float cc = s_c1[w], ss = s_s1[w];
            float xn = vx[w + 1], yn = vy[w + 1], zn = vz[w + 1];
            float cx = cc * xn, cy = cc * yn, cz = cc * zn;
            float sx = ss * xn, sy = ss * yn, sz = ss * zn;
#pragma unroll
            for (int r = 0; r < 4; r++) {
                float aI = A[r][0], aX = A[r][1], aY = A[r][2], aZ = A[r][3];
                A[r][0] = cc * aZ + sx * aY;
                A[r][1] = cx * aZ + ss * aY;
                A[r][2] = cy * aI - sz * aX;
                A[r][3] = cz * aI + sy * aX;
            }
            q[w] = Zt[w] * (s10 * A[2][3] + c10 * A[3][3]);
        }
        float c17 = s_c1[7], s17 = s_s1[7];
        q[7] = c17 * (s10 * A[2][0] + c10 * A[3][0]) + s17 * (c10 * A[2][1] - s10 * A[3][1]);
        q[0] = c17 * A[0][3] + s17 * A[1][2];

        // qs[tid*8+w] == row-major [row_local=tid/8][k=(tid%8)*8+w]
        float4* qo = reinterpret_cast<float4*>(qs + tid * 8);
        qo[0] = make_float4(q[0], q[1], q[2], q[3]);
        qo[1] = make_float4(q[4], q[5], q[6], q[7]);
    } else {
        // ---- park W into swizzled shared (loads landed during phase 1 ramp) ----
        int wt = tid - 128;
#pragma unroll
        for (int i = 0; i < 8; i++) {
            int m = wt + i * 128;           // float4 index = j*16 + c
            int j = m >> 4, c = m & 15;
            Ws4[j * 16 + (c ^ (j & 7))] = wreg[i];
        }
    }
    __syncthreads();

    // ---- Phase 2: 4 outputs/thread, f32x2 packed MACs ----
    int j = tid & 63, g = tid >> 6;        // col j; rows g*4 .. g*4+3
    const float4* q4 = reinterpret_cast<const float4*>(qs) + g * 64;

    ull acc[4] = {0, 0, 0, 0};
#pragma unroll
    for (int c = 0; c < 16; c++) {
        float4 wv = Ws4[j * 16 + (c ^ (j & 7))];   // conflict-free (swizzled)
        ull w01 = pk(wv.x, wv.y), w23 = pk(wv.z, wv.w);
#pragma unroll
        for (int r = 0; r < 4; r++) {
            float4 a = q4[r * 16 + c];             // warp-broadcast LDS
            acc[r] = f2fma(pk(a.x, a.y), w01, acc[r]);
            acc[r] = f2fma(pk(a.z, a.w), w23, acc[r]);
        }
    }
    int row0 = blockIdx.x * 16 + g * 4;
#pragma unroll
    for (int r = 0; r < 4; r++) {
        float lo, hi; upk(acc[r], lo, hi);
        out[(row0 + r) * 64 + j] = lo + hi;
    }
}

extern "C" void kernel_launch(void* const* d_in, const int* in_sizes, int n_in,
                              void* d_out, int out_size) {
    const float* x   = (const float*)d_in[0];
    const float* prx = (const float*)d_in[1];
    const float* prz = (const float*)d_in[2];
    const float* W   = (const float*)d_in[3];
    float* out = (float*)d_out;

    int n_tok = in_sizes[0] / 8;                    // 16384 tokens
    qmha_fused<<<n_tok / 128, 256>>>(x, prx, prz, W, out);  // 128 blocks, 1 wave
}